// round 8
// baseline (speedup 1.0000x reference)
#include <cuda_runtime.h>
#include <cuda_fp16.h>
#include <cstdint>

#define N_NODES    50000
#define OUT_DIM    128
#define IN_DIM     256
#define NNZ_MAX    800000
#define NB_PER_REL 196                     // ceil(50000/256) blocks per relation
#define NPB        256                     // nodes per scan block

// ---------------------------------------------------------------------------
// Device-global scratch. Referenced only from device code.
// ---------------------------------------------------------------------------
__device__ uint2 g_xw1h[(size_t)N_NODES * 32];
__device__ uint2 g_xw2h[(size_t)N_NODES * 32];
__device__ uint2 g_w1h[IN_DIM * 32];           // fp16 copy of W1 [256,128]
__device__ uint2 g_w2h[IN_DIM * 32];

// Per-relation CSR build state. rel: 0=feat, 1=adj1, 2=adj2
__device__ int      g_cnt[3 * N_NODES];        // histogram -> scatter cursors
__device__ int      g_rowptr[3 * (N_NODES + 1)];
__device__ int      g_blocksum[3 * NB_PER_REL];   // raw per-block sums
__device__ unsigned g_pack[3 * (size_t)NNZ_MAX];  // {fp16 val | 16-bit col}

// ---------------------------------------------------------------------------
// helpers
// ---------------------------------------------------------------------------
__device__ __forceinline__ void fma4(float4& a, float v, const float4& w) {
    a.x += v * w.x; a.y += v * w.y; a.z += v * w.z; a.w += v * w.w;
}
__device__ __forceinline__ float4 h4_to_f4(uint2 u) {
    float2 f01 = __half22float2(*reinterpret_cast<__half2*>(&u.x));
    float2 f23 = __half22float2(*reinterpret_cast<__half2*>(&u.y));
    return make_float4(f01.x, f01.y, f23.x, f23.y);
}
__device__ __forceinline__ uint2 f4_to_h4(float4 f) {
    __half2 h01 = __floats2half2_rn(f.x, f.y);
    __half2 h23 = __floats2half2_rn(f.z, f.w);
    uint2 u;
    u.x = *reinterpret_cast<unsigned*>(&h01);
    u.y = *reinterpret_cast<unsigned*>(&h23);
    return u;
}
__device__ __forceinline__ float pack_val(unsigned p) {
    return __half2float(__ushort_as_half((unsigned short)(p >> 16)));
}
__device__ __forceinline__ unsigned make_pack(int c, float v) {
    unsigned hv = (unsigned)__half_as_ushort(__float2half_rn(v));
    return (hv << 16) | (unsigned)c;
}

// ---------------------------------------------------------------------------
// 1) zero counters + convert W1/W2 to fp16
// ---------------------------------------------------------------------------
__global__ void prep_kernel(const float* __restrict__ W1,
                            const float* __restrict__ W2) {
    int stride = gridDim.x * blockDim.x;
    int tid = blockIdx.x * blockDim.x + threadIdx.x;
    for (int i = tid; i < 3 * N_NODES; i += stride)
        g_cnt[i] = 0;
    for (int i = tid; i < IN_DIM * 32; i += stride) {
        g_w1h[i] = f4_to_h4(reinterpret_cast<const float4*>(W1)[i]);
        g_w2h[i] = f4_to_h4(reinterpret_cast<const float4*>(W2)[i]);
    }
}

// ---------------------------------------------------------------------------
// 2) histogram of rows, int4-vectorized (4 independent atomics in flight)
// ---------------------------------------------------------------------------
__device__ __forceinline__ void hist_one(const int* __restrict__ rows, int n,
                                         int rel, int tid, int nthreads) {
    int n4 = n >> 2;
    const int4* r4 = reinterpret_cast<const int4*>(rows);
    int* cnt = g_cnt + rel * N_NODES;
    for (int i = tid; i < n4; i += nthreads) {
        int4 q = r4[i];
        atomicAdd(&cnt[q.x], 1);
        atomicAdd(&cnt[q.y], 1);
        atomicAdd(&cnt[q.z], 1);
        atomicAdd(&cnt[q.w], 1);
    }
    for (int i = (n4 << 2) + tid; i < n; i += nthreads)
        atomicAdd(&cnt[rows[i]], 1);
}

__global__ void hist_kernel(const int* __restrict__ frow,
                            const int* __restrict__ a1row,
                            const int* __restrict__ a2row,
                            int nf, int n1, int n2) {
    int tid = blockIdx.x * blockDim.x + threadIdx.x;
    int nthreads = gridDim.x * blockDim.x;
    hist_one(frow,  nf, 0, tid, nthreads);
    hist_one(a1row, n1, 1, tid, nthreads);
    hist_one(a2row, n2, 2, tid, nthreads);
}

// ---------------------------------------------------------------------------
// 3a) block-local exclusive scan (warp-shuffle, 2 barriers).
//     Exclusive-in-block -> g_rowptr (temp); block total -> g_blocksum.
// ---------------------------------------------------------------------------
__global__ void scanA_kernel() {
    __shared__ int sh_warp[NPB / 32];
    int rel  = blockIdx.x / NB_PER_REL;
    int blk  = blockIdx.x % NB_PER_REL;
    int t    = threadIdx.x;
    int lane = t & 31;
    int w    = t >> 5;
    int idx  = blk * NPB + t;

    int v = (idx < N_NODES) ? g_cnt[rel * N_NODES + idx] : 0;

    int x = v;
    #pragma unroll
    for (int off = 1; off < 32; off <<= 1) {
        int tmp = __shfl_up_sync(0xffffffff, x, off);
        if (lane >= off) x += tmp;
    }
    if (lane == 31) sh_warp[w] = x;
    __syncthreads();
    if (w == 0) {
        int y = (lane < NPB / 32) ? sh_warp[lane] : 0;
        #pragma unroll
        for (int off = 1; off < NPB / 32; off <<= 1) {
            int tmp = __shfl_up_sync(0xffffffff, y, off);
            if (lane >= off) y += tmp;
        }
        if (lane < NPB / 32) sh_warp[lane] = y;
    }
    __syncthreads();
    int incl = x + (w ? sh_warp[w - 1] : 0);

    if (idx < N_NODES)
        g_rowptr[rel * (N_NODES + 1) + idx] = incl - v;   // exclusive in block
    if (t == NPB - 1)
        g_blocksum[rel * NB_PER_REL + blk] = incl;        // block total
}

// ---------------------------------------------------------------------------
// 3b) finalize: each block reduces its predecessors' block sums itself
//     (<=196 values, warp-parallel), then writes rowptr + cursors + totals.
// ---------------------------------------------------------------------------
__global__ void scanC_kernel() {
    __shared__ int sh_off;
    int rel = blockIdx.x / NB_PER_REL;
    int blk = blockIdx.x % NB_PER_REL;
    int t   = threadIdx.x;

    if (t < 32) {
        int s = 0;
        const int* bs = g_blocksum + rel * NB_PER_REL;
        for (int j = t; j < blk; j += 32) s += bs[j];
        #pragma unroll
        for (int o = 16; o; o >>= 1) s += __shfl_down_sync(0xffffffff, s, o);
        if (t == 0) sh_off = s;
    }
    __syncthreads();

    int idx = blk * NPB + t;
    if (idx >= N_NODES) return;

    int excl = g_rowptr[rel * (N_NODES + 1) + idx] + sh_off;
    int orig = g_cnt[rel * N_NODES + idx];

    g_rowptr[rel * (N_NODES + 1) + idx] = excl;
    g_cnt[rel * N_NODES + idx]          = excl;   // scatter cursor
    if (idx == N_NODES - 1)
        g_rowptr[rel * (N_NODES + 1) + N_NODES] = excl + orig;
}

// ---------------------------------------------------------------------------
// 4) scatter, vectorized: 4 edges per iteration
// ---------------------------------------------------------------------------
__device__ __forceinline__ void scatter_one(const int* __restrict__ rows,
                                            const int* __restrict__ cols,
                                            const float* __restrict__ vals,
                                            int n, int rel, int tid, int nthreads) {
    int* cnt = g_cnt + rel * N_NODES;
    unsigned* pk = g_pack + (size_t)rel * NNZ_MAX;
    int n4 = n >> 2;
    const int4*   r4 = reinterpret_cast<const int4*>(rows);
    const int4*   c4 = reinterpret_cast<const int4*>(cols);
    const float4* v4 = reinterpret_cast<const float4*>(vals);
    for (int i = tid; i < n4; i += nthreads) {
        int4   r = r4[i];
        int4   c = c4[i];
        float4 v = v4[i];
        int p0 = atomicAdd(&cnt[r.x], 1);
        int p1 = atomicAdd(&cnt[r.y], 1);
        int p2 = atomicAdd(&cnt[r.z], 1);
        int p3 = atomicAdd(&cnt[r.w], 1);
        pk[p0] = make_pack(c.x, v.x);
        pk[p1] = make_pack(c.y, v.y);
        pk[p2] = make_pack(c.z, v.z);
        pk[p3] = make_pack(c.w, v.w);
    }
    for (int i = (n4 << 2) + tid; i < n; i += nthreads) {
        int pos = atomicAdd(&cnt[rows[i]], 1);
        pk[pos] = make_pack(cols[i], vals[i]);
    }
}

__global__ void scatter_kernel(const int* __restrict__ frow, const int* __restrict__ fcol,
                               const float* __restrict__ fval,
                               const int* __restrict__ a1row, const int* __restrict__ a1col,
                               const float* __restrict__ a1val,
                               const int* __restrict__ a2row, const int* __restrict__ a2col,
                               const float* __restrict__ a2val,
                               int nf, int n1, int n2) {
    int tid = blockIdx.x * blockDim.x + threadIdx.x;
    int nthreads = gridDim.x * blockDim.x;
    scatter_one(frow,  fcol,  fval,  nf, 0, tid, nthreads);
    scatter_one(a1row, a1col, a1val, n1, 1, tid, nthreads);
    scatter_one(a2row, a2col, a2val, n2, 2, tid, nthreads);
}

// ---------------------------------------------------------------------------
// 5) feature SpMM, CSR: one warp per node, fp16 W gathers (L1-hot),
//    fp32 accumulate, fp16 stores. Unroll-4 for MLP.
// ---------------------------------------------------------------------------
__global__ void feat_csr_kernel() {
    int r    = (blockIdx.x * blockDim.x + threadIdx.x) >> 5;
    int lane = threadIdx.x & 31;
    if (r >= N_NODES) return;

    int s = g_rowptr[r], e = g_rowptr[r + 1];
    const unsigned* pk = g_pack;  // rel 0

    float4 acc1 = make_float4(0.f, 0.f, 0.f, 0.f);
    float4 acc2 = make_float4(0.f, 0.f, 0.f, 0.f);

    int i = s;
    for (; i + 4 <= e; i += 4) {
        unsigned p0 = pk[i], p1 = pk[i + 1], p2 = pk[i + 2], p3 = pk[i + 3];
        int c0 = p0 & 0xFFFF, c1 = p1 & 0xFFFF, c2 = p2 & 0xFFFF, c3 = p3 & 0xFFFF;
        uint2 a0 = g_w1h[c0 * 32 + lane], b0 = g_w2h[c0 * 32 + lane];
        uint2 a1 = g_w1h[c1 * 32 + lane], b1 = g_w2h[c1 * 32 + lane];
        uint2 a2 = g_w1h[c2 * 32 + lane], b2 = g_w2h[c2 * 32 + lane];
        uint2 a3 = g_w1h[c3 * 32 + lane], b3 = g_w2h[c3 * 32 + lane];
        float v0 = pack_val(p0), v1 = pack_val(p1), v2 = pack_val(p2), v3 = pack_val(p3);
        fma4(acc1, v0, h4_to_f4(a0)); fma4(acc2, v0, h4_to_f4(b0));
        fma4(acc1, v1, h4_to_f4(a1)); fma4(acc2, v1, h4_to_f4(b1));
        fma4(acc1, v2, h4_to_f4(a2)); fma4(acc2, v2, h4_to_f4(b2));
        fma4(acc1, v3, h4_to_f4(a3)); fma4(acc2, v3, h4_to_f4(b3));
    }
    for (; i < e; i++) {
        unsigned p = pk[i];
        int c = p & 0xFFFF;
        float v = pack_val(p);
        fma4(acc1, v, h4_to_f4(g_w1h[c * 32 + lane]));
        fma4(acc2, v, h4_to_f4(g_w2h[c * 32 + lane]));
    }
    g_xw1h[(size_t)r * 32 + lane] = f4_to_h4(acc1);
    g_xw2h[(size_t)r * 32 + lane] = f4_to_h4(acc2);
}

// ---------------------------------------------------------------------------
// 6) adjacency SpMM (both relations) + relu: one warp per node, unroll-4,
//    fp16 gathers (L2-resident), fp32 accumulate, fp32 output.
// ---------------------------------------------------------------------------
template <int REL>
__device__ __forceinline__ void adj_accum(int r, int lane, const uint2* __restrict__ H,
                                          float4& acc) {
    const int* rp = g_rowptr + REL * (N_NODES + 1);
    int s = rp[r], e = rp[r + 1];
    const unsigned* pk = g_pack + REL * (size_t)NNZ_MAX;

    int i = s;
    for (; i + 4 <= e; i += 4) {
        unsigned p0 = pk[i], p1 = pk[i + 1], p2 = pk[i + 2], p3 = pk[i + 3];
        uint2 h0 = H[(size_t)(p0 & 0xFFFF) * 32 + lane];
        uint2 h1 = H[(size_t)(p1 & 0xFFFF) * 32 + lane];
        uint2 h2 = H[(size_t)(p2 & 0xFFFF) * 32 + lane];
        uint2 h3 = H[(size_t)(p3 & 0xFFFF) * 32 + lane];
        fma4(acc, pack_val(p0), h4_to_f4(h0));
        fma4(acc, pack_val(p1), h4_to_f4(h1));
        fma4(acc, pack_val(p2), h4_to_f4(h2));
        fma4(acc, pack_val(p3), h4_to_f4(h3));
    }
    for (; i < e; i++) {
        unsigned p = pk[i];
        fma4(acc, pack_val(p), h4_to_f4(H[(size_t)(p & 0xFFFF) * 32 + lane]));
    }
}

__global__ void adj_relu_kernel(float* __restrict__ out) {
    int r    = (blockIdx.x * blockDim.x + threadIdx.x) >> 5;
    int lane = threadIdx.x & 31;
    if (r >= N_NODES) return;

    float4 acc = make_float4(0.f, 0.f, 0.f, 0.f);
    adj_accum<1>(r, lane, g_xw1h, acc);
    adj_accum<2>(r, lane, g_xw2h, acc);

    acc.x = fmaxf(acc.x, 0.f);
    acc.y = fmaxf(acc.y, 0.f);
    acc.z = fmaxf(acc.z, 0.f);
    acc.w = fmaxf(acc.w, 0.f);
    reinterpret_cast<float4*>(out + (size_t)r * OUT_DIM)[lane] = acc;
}

// ---------------------------------------------------------------------------
// Launch. Input order: feat_row, feat_col, feat_vals, adj1_row, adj1_col,
// adj1_vals, adj2_row, adj2_col, adj2_vals, W1, W2, n_nodes
// ---------------------------------------------------------------------------
extern "C" void kernel_launch(void* const* d_in, const int* in_sizes, int n_in,
                              void* d_out, int out_size) {
    const int*   feat_row = (const int*)  d_in[0];
    const int*   feat_col = (const int*)  d_in[1];
    const float* feat_val = (const float*)d_in[2];
    const int*   a1_row   = (const int*)  d_in[3];
    const int*   a1_col   = (const int*)  d_in[4];
    const float* a1_val   = (const float*)d_in[5];
    const int*   a2_row   = (const int*)  d_in[6];
    const int*   a2_col   = (const int*)  d_in[7];
    const float* a2_val   = (const float*)d_in[8];
    const float* W1       = (const float*)d_in[9];
    const float* W2       = (const float*)d_in[10];
    float* out = (float*)d_out;

    const int nf = in_sizes[0];
    const int n1 = in_sizes[3];
    const int n2 = in_sizes[6];

    prep_kernel<<<256, 256>>>(W1, W2);
    hist_kernel<<<512, 256>>>(feat_row, a1_row, a2_row, nf, n1, n2);
    scanA_kernel<<<3 * NB_PER_REL, NPB>>>();
    scanC_kernel<<<3 * NB_PER_REL, NPB>>>();
    scatter_kernel<<<512, 256>>>(feat_row, feat_col, feat_val,
                                 a1_row, a1_col, a1_val,
                                 a2_row, a2_col, a2_val,
                                 nf, n1, n2);

    const int node_blocks = (N_NODES + 7) / 8;
    feat_csr_kernel<<<node_blocks, 256>>>();
    adj_relu_kernel<<<node_blocks, 256>>>(out);
}

// round 9
// speedup vs baseline: 1.0819x; 1.0819x over previous
#include <cuda_runtime.h>
#include <cuda_fp16.h>
#include <cstdint>

#define N_NODES    50000
#define OUT_DIM    128
#define IN_DIM     256
#define NNZ_MAX    800000
#define NB_PER_REL 196                     // ceil(50000/256) blocks per relation
#define NPB        256                     // nodes per scan block

// ---------------------------------------------------------------------------
// Device-global scratch. Referenced only from device code.
// ---------------------------------------------------------------------------
__device__ uint2 g_xw1h[(size_t)N_NODES * 32];
__device__ uint2 g_xw2h[(size_t)N_NODES * 32];
__device__ uint2 g_w1h[IN_DIM * 32];           // fp16 copy of W1 [256,128]
__device__ uint2 g_w2h[IN_DIM * 32];

// Per-relation CSR build state. rel: 0=feat, 1=adj1, 2=adj2
__device__ int      g_cnt[3 * N_NODES];        // histogram -> scatter cursors
__device__ int      g_rowptr[3 * (N_NODES + 1)];
__device__ int      g_blocksum[3 * NB_PER_REL];   // raw per-block sums
__device__ unsigned g_pack[3 * (size_t)NNZ_MAX];  // {fp16 val | 16-bit col}

// ---------------------------------------------------------------------------
// helpers
// ---------------------------------------------------------------------------
__device__ __forceinline__ void fma4(float4& a, float v, const float4& w) {
    a.x += v * w.x; a.y += v * w.y; a.z += v * w.z; a.w += v * w.w;
}
__device__ __forceinline__ float4 h4_to_f4(uint2 u) {
    float2 f01 = __half22float2(*reinterpret_cast<__half2*>(&u.x));
    float2 f23 = __half22float2(*reinterpret_cast<__half2*>(&u.y));
    return make_float4(f01.x, f01.y, f23.x, f23.y);
}
__device__ __forceinline__ uint2 f4_to_h4(float4 f) {
    __half2 h01 = __floats2half2_rn(f.x, f.y);
    __half2 h23 = __floats2half2_rn(f.z, f.w);
    uint2 u;
    u.x = *reinterpret_cast<unsigned*>(&h01);
    u.y = *reinterpret_cast<unsigned*>(&h23);
    return u;
}
__device__ __forceinline__ float pack_val(unsigned p) {
    return __half2float(__ushort_as_half((unsigned short)(p >> 16)));
}
__device__ __forceinline__ unsigned make_pack(int c, float v) {
    unsigned hv = (unsigned)__half_as_ushort(__float2half_rn(v));
    return (hv << 16) | (unsigned)c;
}

// ---------------------------------------------------------------------------
// 1a) zero histogram counters (critical path)
// ---------------------------------------------------------------------------
__global__ void zero_cnt_kernel() {
    int stride = gridDim.x * blockDim.x;
    for (int i = blockIdx.x * blockDim.x + threadIdx.x; i < 3 * N_NODES; i += stride)
        g_cnt[i] = 0;
}

// ---------------------------------------------------------------------------
// 1b) convert W1/W2 to fp16 (side stream; only needed before feat)
// ---------------------------------------------------------------------------
__global__ void wconv_kernel(const float* __restrict__ W1,
                             const float* __restrict__ W2) {
    int i = blockIdx.x * blockDim.x + threadIdx.x;
    if (i < IN_DIM * 32) {
        g_w1h[i] = f4_to_h4(reinterpret_cast<const float4*>(W1)[i]);
        g_w2h[i] = f4_to_h4(reinterpret_cast<const float4*>(W2)[i]);
    }
}

// ---------------------------------------------------------------------------
// 2) histogram of rows, int4-vectorized (4 independent atomics in flight)
// ---------------------------------------------------------------------------
__device__ __forceinline__ void hist_one(const int* __restrict__ rows, int n,
                                         int rel, int tid, int nthreads) {
    int n4 = n >> 2;
    const int4* r4 = reinterpret_cast<const int4*>(rows);
    int* cnt = g_cnt + rel * N_NODES;
    for (int i = tid; i < n4; i += nthreads) {
        int4 q = r4[i];
        atomicAdd(&cnt[q.x], 1);
        atomicAdd(&cnt[q.y], 1);
        atomicAdd(&cnt[q.z], 1);
        atomicAdd(&cnt[q.w], 1);
    }
    for (int i = (n4 << 2) + tid; i < n; i += nthreads)
        atomicAdd(&cnt[rows[i]], 1);
}

__global__ void hist_kernel(const int* __restrict__ frow,
                            const int* __restrict__ a1row,
                            const int* __restrict__ a2row,
                            int nf, int n1, int n2) {
    int tid = blockIdx.x * blockDim.x + threadIdx.x;
    int nthreads = gridDim.x * blockDim.x;
    hist_one(frow,  nf, 0, tid, nthreads);
    hist_one(a1row, n1, 1, tid, nthreads);
    hist_one(a2row, n2, 2, tid, nthreads);
}

// ---------------------------------------------------------------------------
// 3a) block-local exclusive scan (warp-shuffle).
// ---------------------------------------------------------------------------
__global__ void scanA_kernel() {
    __shared__ int sh_warp[NPB / 32];
    int rel  = blockIdx.x / NB_PER_REL;
    int blk  = blockIdx.x % NB_PER_REL;
    int t    = threadIdx.x;
    int lane = t & 31;
    int w    = t >> 5;
    int idx  = blk * NPB + t;

    int v = (idx < N_NODES) ? g_cnt[rel * N_NODES + idx] : 0;

    int x = v;
    #pragma unroll
    for (int off = 1; off < 32; off <<= 1) {
        int tmp = __shfl_up_sync(0xffffffff, x, off);
        if (lane >= off) x += tmp;
    }
    if (lane == 31) sh_warp[w] = x;
    __syncthreads();
    if (w == 0) {
        int y = (lane < NPB / 32) ? sh_warp[lane] : 0;
        #pragma unroll
        for (int off = 1; off < NPB / 32; off <<= 1) {
            int tmp = __shfl_up_sync(0xffffffff, y, off);
            if (lane >= off) y += tmp;
        }
        if (lane < NPB / 32) sh_warp[lane] = y;
    }
    __syncthreads();
    int incl = x + (w ? sh_warp[w - 1] : 0);

    if (idx < N_NODES)
        g_rowptr[rel * (N_NODES + 1) + idx] = incl - v;   // exclusive in block
    if (t == NPB - 1)
        g_blocksum[rel * NB_PER_REL + blk] = incl;        // block total
}

// ---------------------------------------------------------------------------
// 3b) finalize: each block reduces its predecessors' block sums itself,
//     then writes rowptr + cursors + totals.
// ---------------------------------------------------------------------------
__global__ void scanC_kernel() {
    __shared__ int sh_off;
    int rel = blockIdx.x / NB_PER_REL;
    int blk = blockIdx.x % NB_PER_REL;
    int t   = threadIdx.x;

    if (t < 32) {
        int s = 0;
        const int* bs = g_blocksum + rel * NB_PER_REL;
        for (int j = t; j < blk; j += 32) s += bs[j];
        #pragma unroll
        for (int o = 16; o; o >>= 1) s += __shfl_down_sync(0xffffffff, s, o);
        if (t == 0) sh_off = s;
    }
    __syncthreads();

    int idx = blk * NPB + t;
    if (idx >= N_NODES) return;

    int excl = g_rowptr[rel * (N_NODES + 1) + idx] + sh_off;
    int orig = g_cnt[rel * N_NODES + idx];

    g_rowptr[rel * (N_NODES + 1) + idx] = excl;
    g_cnt[rel * N_NODES + idx]          = excl;   // scatter cursor
    if (idx == N_NODES - 1)
        g_rowptr[rel * (N_NODES + 1) + N_NODES] = excl + orig;
}

// ---------------------------------------------------------------------------
// 4) scatter, vectorized: 4 edges per iteration
// ---------------------------------------------------------------------------
__device__ __forceinline__ void scatter_one(const int* __restrict__ rows,
                                            const int* __restrict__ cols,
                                            const float* __restrict__ vals,
                                            int n, int rel, int tid, int nthreads) {
    int* cnt = g_cnt + rel * N_NODES;
    unsigned* pk = g_pack + (size_t)rel * NNZ_MAX;
    int n4 = n >> 2;
    const int4*   r4 = reinterpret_cast<const int4*>(rows);
    const int4*   c4 = reinterpret_cast<const int4*>(cols);
    const float4* v4 = reinterpret_cast<const float4*>(vals);
    for (int i = tid; i < n4; i += nthreads) {
        int4   r = r4[i];
        int4   c = c4[i];
        float4 v = v4[i];
        int p0 = atomicAdd(&cnt[r.x], 1);
        int p1 = atomicAdd(&cnt[r.y], 1);
        int p2 = atomicAdd(&cnt[r.z], 1);
        int p3 = atomicAdd(&cnt[r.w], 1);
        pk[p0] = make_pack(c.x, v.x);
        pk[p1] = make_pack(c.y, v.y);
        pk[p2] = make_pack(c.z, v.z);
        pk[p3] = make_pack(c.w, v.w);
    }
    for (int i = (n4 << 2) + tid; i < n; i += nthreads) {
        int pos = atomicAdd(&cnt[rows[i]], 1);
        pk[pos] = make_pack(cols[i], vals[i]);
    }
}

__global__ void scatter_feat_kernel(const int* __restrict__ frow,
                                    const int* __restrict__ fcol,
                                    const float* __restrict__ fval, int nf) {
    int tid = blockIdx.x * blockDim.x + threadIdx.x;
    int nthreads = gridDim.x * blockDim.x;
    scatter_one(frow, fcol, fval, nf, 0, tid, nthreads);
}

__global__ void scatter_adj_kernel(const int* __restrict__ a1row, const int* __restrict__ a1col,
                                   const float* __restrict__ a1val,
                                   const int* __restrict__ a2row, const int* __restrict__ a2col,
                                   const float* __restrict__ a2val,
                                   int n1, int n2) {
    int tid = blockIdx.x * blockDim.x + threadIdx.x;
    int nthreads = gridDim.x * blockDim.x;
    scatter_one(a1row, a1col, a1val, n1, 1, tid, nthreads);
    scatter_one(a2row, a2col, a2val, n2, 2, tid, nthreads);
}

// ---------------------------------------------------------------------------
// 5) feature SpMM, CSR: one warp per node, fp16 W gathers (L1-hot),
//    fp32 accumulate, fp16 stores. Unroll-4 for MLP.
// ---------------------------------------------------------------------------
__global__ void feat_csr_kernel() {
    int r    = (blockIdx.x * blockDim.x + threadIdx.x) >> 5;
    int lane = threadIdx.x & 31;
    if (r >= N_NODES) return;

    int s = g_rowptr[r], e = g_rowptr[r + 1];
    const unsigned* pk = g_pack;  // rel 0

    float4 acc1 = make_float4(0.f, 0.f, 0.f, 0.f);
    float4 acc2 = make_float4(0.f, 0.f, 0.f, 0.f);

    int i = s;
    for (; i + 4 <= e; i += 4) {
        unsigned p0 = pk[i], p1 = pk[i + 1], p2 = pk[i + 2], p3 = pk[i + 3];
        int c0 = p0 & 0xFFFF, c1 = p1 & 0xFFFF, c2 = p2 & 0xFFFF, c3 = p3 & 0xFFFF;
        uint2 a0 = g_w1h[c0 * 32 + lane], b0 = g_w2h[c0 * 32 + lane];
        uint2 a1 = g_w1h[c1 * 32 + lane], b1 = g_w2h[c1 * 32 + lane];
        uint2 a2 = g_w1h[c2 * 32 + lane], b2 = g_w2h[c2 * 32 + lane];
        uint2 a3 = g_w1h[c3 * 32 + lane], b3 = g_w2h[c3 * 32 + lane];
        float v0 = pack_val(p0), v1 = pack_val(p1), v2 = pack_val(p2), v3 = pack_val(p3);
        fma4(acc1, v0, h4_to_f4(a0)); fma4(acc2, v0, h4_to_f4(b0));
        fma4(acc1, v1, h4_to_f4(a1)); fma4(acc2, v1, h4_to_f4(b1));
        fma4(acc1, v2, h4_to_f4(a2)); fma4(acc2, v2, h4_to_f4(b2));
        fma4(acc1, v3, h4_to_f4(a3)); fma4(acc2, v3, h4_to_f4(b3));
    }
    for (; i < e; i++) {
        unsigned p = pk[i];
        int c = p & 0xFFFF;
        float v = pack_val(p);
        fma4(acc1, v, h4_to_f4(g_w1h[c * 32 + lane]));
        fma4(acc2, v, h4_to_f4(g_w2h[c * 32 + lane]));
    }
    g_xw1h[(size_t)r * 32 + lane] = f4_to_h4(acc1);
    g_xw2h[(size_t)r * 32 + lane] = f4_to_h4(acc2);
}

// ---------------------------------------------------------------------------
// 6) adjacency SpMM (both relations) + relu: one warp per node, unroll-4.
// ---------------------------------------------------------------------------
template <int REL>
__device__ __forceinline__ void adj_accum(int r, int lane, const uint2* __restrict__ H,
                                          float4& acc) {
    const int* rp = g_rowptr + REL * (N_NODES + 1);
    int s = rp[r], e = rp[r + 1];
    const unsigned* pk = g_pack + REL * (size_t)NNZ_MAX;

    int i = s;
    for (; i + 4 <= e; i += 4) {
        unsigned p0 = pk[i], p1 = pk[i + 1], p2 = pk[i + 2], p3 = pk[i + 3];
        uint2 h0 = H[(size_t)(p0 & 0xFFFF) * 32 + lane];
        uint2 h1 = H[(size_t)(p1 & 0xFFFF) * 32 + lane];
        uint2 h2 = H[(size_t)(p2 & 0xFFFF) * 32 + lane];
        uint2 h3 = H[(size_t)(p3 & 0xFFFF) * 32 + lane];
        fma4(acc, pack_val(p0), h4_to_f4(h0));
        fma4(acc, pack_val(p1), h4_to_f4(h1));
        fma4(acc, pack_val(p2), h4_to_f4(h2));
        fma4(acc, pack_val(p3), h4_to_f4(h3));
    }
    for (; i < e; i++) {
        unsigned p = pk[i];
        fma4(acc, pack_val(p), h4_to_f4(H[(size_t)(p & 0xFFFF) * 32 + lane]));
    }
}

__global__ void adj_relu_kernel(float* __restrict__ out) {
    int r    = (blockIdx.x * blockDim.x + threadIdx.x) >> 5;
    int lane = threadIdx.x & 31;
    if (r >= N_NODES) return;

    float4 acc = make_float4(0.f, 0.f, 0.f, 0.f);
    adj_accum<1>(r, lane, g_xw1h, acc);
    adj_accum<2>(r, lane, g_xw2h, acc);

    acc.x = fmaxf(acc.x, 0.f);
    acc.y = fmaxf(acc.y, 0.f);
    acc.z = fmaxf(acc.z, 0.f);
    acc.w = fmaxf(acc.w, 0.f);
    reinterpret_cast<float4*>(out + (size_t)r * OUT_DIM)[lane] = acc;
}

// ---------------------------------------------------------------------------
// Launch. Two-stream fork/join: the adj scatter (LTS-bound) overlaps the
// feat scatter + feat SpMM (L1-bound) on the capture stream.
// Streams/events created once on the first (uncaptured) call.
// ---------------------------------------------------------------------------
extern "C" void kernel_launch(void* const* d_in, const int* in_sizes, int n_in,
                              void* d_out, int out_size) {
    const int*   feat_row = (const int*)  d_in[0];
    const int*   feat_col = (const int*)  d_in[1];
    const float* feat_val = (const float*)d_in[2];
    const int*   a1_row   = (const int*)  d_in[3];
    const int*   a1_col   = (const int*)  d_in[4];
    const float* a1_val   = (const float*)d_in[5];
    const int*   a2_row   = (const int*)  d_in[6];
    const int*   a2_col   = (const int*)  d_in[7];
    const float* a2_val   = (const float*)d_in[8];
    const float* W1       = (const float*)d_in[9];
    const float* W2       = (const float*)d_in[10];
    float* out = (float*)d_out;

    const int nf = in_sizes[0];
    const int n1 = in_sizes[3];
    const int n2 = in_sizes[6];

    static cudaStream_t s1 = nullptr;
    static cudaEvent_t evFork = nullptr, evW = nullptr, evCsr = nullptr, evS12 = nullptr;
    if (!s1) {
        cudaStreamCreateWithFlags(&s1, cudaStreamNonBlocking);
        cudaEventCreateWithFlags(&evFork, cudaEventDisableTiming);
        cudaEventCreateWithFlags(&evW,    cudaEventDisableTiming);
        cudaEventCreateWithFlags(&evCsr,  cudaEventDisableTiming);
        cudaEventCreateWithFlags(&evS12,  cudaEventDisableTiming);
    }

    // fork: side stream does the W conversion immediately
    cudaEventRecord(evFork, 0);
    cudaStreamWaitEvent(s1, evFork, 0);
    wconv_kernel<<<32, 256, 0, s1>>>(W1, W2);
    cudaEventRecord(evW, s1);

    // main stream: CSR build
    zero_cnt_kernel<<<256, 256>>>();
    hist_kernel<<<512, 256>>>(feat_row, a1_row, a2_row, nf, n1, n2);
    scanA_kernel<<<3 * NB_PER_REL, NPB>>>();
    scanC_kernel<<<3 * NB_PER_REL, NPB>>>();
    cudaEventRecord(evCsr, 0);

    // side stream: adj scatter overlaps feat scatter + feat SpMM
    cudaStreamWaitEvent(s1, evCsr, 0);
    scatter_adj_kernel<<<512, 256, 0, s1>>>(a1_row, a1_col, a1_val,
                                            a2_row, a2_col, a2_val, n1, n2);
    cudaEventRecord(evS12, s1);

    // main stream: feat scatter, feat SpMM
    scatter_feat_kernel<<<512, 256>>>(feat_row, feat_col, feat_val, nf);
    cudaStreamWaitEvent(0, evW, 0);
    const int node_blocks = (N_NODES + 7) / 8;
    feat_csr_kernel<<<node_blocks, 256>>>();

    // join: adj needs both feat output (stream 0) and adj CSR (s1)
    cudaStreamWaitEvent(0, evS12, 0);
    adj_relu_kernel<<<node_blocks, 256>>>(out);
}